// round 3
// baseline (speedup 1.0000x reference)
#include <cuda_runtime.h>
#include <math.h>

#define NN 4096
#define BB 32
#define FF 66
#define UU 64
#define MM 5
#define FB 2112          // FF*BB
#define FB4 528          // FB/4
#define NNZ_MAX 128

// ---------------- scratch ----------------
__device__ float g_X0[(size_t)NN * FB];
__device__ float g_X2[(size_t)NN * FB];
__device__ float g_M[4][(size_t)NN * FB];
__device__ float g_U[(size_t)BB * NN * UU];
__device__ int   g_sidx[2][(size_t)NNZ_MAX * NN];
__device__ float g_sval[2][(size_t)NNZ_MAX * NN];
__device__ int   g_cnt[2][NN];

// ---------------- helpers ----------------
__device__ __forceinline__ unsigned f2tf(float x) {
    unsigned r; asm("cvt.rna.tf32.f32 %0, %1;" : "=r"(r) : "f"(x)); return r;
}
__device__ __forceinline__ void mma_tf32(float* d, const unsigned* a, unsigned b0, unsigned b1) {
    asm volatile(
        "mma.sync.aligned.m16n8k8.row.col.f32.tf32.tf32.f32 "
        "{%0,%1,%2,%3}, {%4,%5,%6,%7}, {%8,%9}, {%0,%1,%2,%3};"
        : "+f"(d[0]), "+f"(d[1]), "+f"(d[2]), "+f"(d[3])
        : "r"(a[0]), "r"(a[1]), "r"(a[2]), "r"(a[3]), "r"(b0), "r"(b1));
}

// ---------------- sparse build ----------------
__global__ void build_sparse_k(const float* __restrict__ S, int sup) {
    int gw   = (blockIdx.x * blockDim.x + threadIdx.x) >> 5;
    int lane = threadIdx.x & 31;
    if (gw >= NN) return;
    const float* row = S + (size_t)gw * NN;
    int* idx = g_sidx[sup];
    float* val = g_sval[sup];
    int c = 0;
    for (int j0 = 0; j0 < NN; j0 += 32) {
        float v = row[j0 + lane];
        unsigned m = __ballot_sync(0xffffffffu, v != 0.0f);
        int pre = __popc(m & ((1u << lane) - 1u));
        if (v != 0.0f) {
            int slot = c + pre;
            if (slot < NNZ_MAX) {
                idx[(size_t)slot * NN + gw] = j0 + lane;
                val[(size_t)slot * NN + gw] = v;
            }
        }
        c += __popc(m);
    }
    if (lane == 0) g_cnt[sup][gw] = (c < NNZ_MAX) ? c : NNZ_MAX;
}

// ---------------- build X0 / static X2 ----------------
__global__ void build_x_k(const float* __restrict__ inp, const float* __restrict__ hx) {
    int e = blockIdx.x * blockDim.x + threadIdx.x;
    if (e >= NN * FB) return;
    int n = e / FB;
    int rem = e - n * FB;
    int b = rem / FF;
    int f = rem - b * FF;
    float v;
    if (f < 2) {
        v = inp[(size_t)b * (NN * 2) + n * 2 + f];
        g_X2[e] = v;
    } else {
        v = hx[(size_t)b * (NN * UU) + (size_t)n * UU + (f - 2)];
    }
    g_X0[e] = v;
}

__device__ __forceinline__ float* sel_buf(int s) {
    if (s == 0) return g_X0;
    if (s == 5) return g_X2;
    return g_M[s - 1];
}

// ---------------- SpMM: 1 row per CTA, 2 float4 cols/thread, unroll 4 ----------
__global__ __launch_bounds__(264) void spmm_k(int sup, int in_sel, int sub_sel,
                                              int out_sel, float alpha) {
    int i = blockIdx.x;
    int c0 = threadIdx.x;       // 0..263
    int c1 = c0 + 264;          // 264..527
    const float4* __restrict__ Xin = (const float4*)sel_buf(in_sel);
    const int*   __restrict__ sidx = g_sidx[sup];
    const float* __restrict__ sval = g_sval[sup];
    int cnt = g_cnt[sup][i];

    float4 A0 = make_float4(0.f, 0.f, 0.f, 0.f);
    float4 A1 = make_float4(0.f, 0.f, 0.f, 0.f);
    int k = 0;
    for (; k + 3 < cnt; k += 4) {
        int j0 = __ldg(&sidx[(size_t)(k + 0) * NN + i]);
        int j1 = __ldg(&sidx[(size_t)(k + 1) * NN + i]);
        int j2 = __ldg(&sidx[(size_t)(k + 2) * NN + i]);
        int j3 = __ldg(&sidx[(size_t)(k + 3) * NN + i]);
        float v0 = __ldg(&sval[(size_t)(k + 0) * NN + i]);
        float v1 = __ldg(&sval[(size_t)(k + 1) * NN + i]);
        float v2 = __ldg(&sval[(size_t)(k + 2) * NN + i]);
        float v3 = __ldg(&sval[(size_t)(k + 3) * NN + i]);
        float4 x00 = __ldg(&Xin[(size_t)j0 * FB4 + c0]);
        float4 x01 = __ldg(&Xin[(size_t)j0 * FB4 + c1]);
        float4 x10 = __ldg(&Xin[(size_t)j1 * FB4 + c0]);
        float4 x11 = __ldg(&Xin[(size_t)j1 * FB4 + c1]);
        float4 x20 = __ldg(&Xin[(size_t)j2 * FB4 + c0]);
        float4 x21 = __ldg(&Xin[(size_t)j2 * FB4 + c1]);
        float4 x30 = __ldg(&Xin[(size_t)j3 * FB4 + c0]);
        float4 x31 = __ldg(&Xin[(size_t)j3 * FB4 + c1]);
        A0.x = fmaf(v0, x00.x, A0.x); A0.y = fmaf(v0, x00.y, A0.y);
        A0.z = fmaf(v0, x00.z, A0.z); A0.w = fmaf(v0, x00.w, A0.w);
        A1.x = fmaf(v0, x01.x, A1.x); A1.y = fmaf(v0, x01.y, A1.y);
        A1.z = fmaf(v0, x01.z, A1.z); A1.w = fmaf(v0, x01.w, A1.w);
        A0.x = fmaf(v1, x10.x, A0.x); A0.y = fmaf(v1, x10.y, A0.y);
        A0.z = fmaf(v1, x10.z, A0.z); A0.w = fmaf(v1, x10.w, A0.w);
        A1.x = fmaf(v1, x11.x, A1.x); A1.y = fmaf(v1, x11.y, A1.y);
        A1.z = fmaf(v1, x11.z, A1.z); A1.w = fmaf(v1, x11.w, A1.w);
        A0.x = fmaf(v2, x20.x, A0.x); A0.y = fmaf(v2, x20.y, A0.y);
        A0.z = fmaf(v2, x20.z, A0.z); A0.w = fmaf(v2, x20.w, A0.w);
        A1.x = fmaf(v2, x21.x, A1.x); A1.y = fmaf(v2, x21.y, A1.y);
        A1.z = fmaf(v2, x21.z, A1.z); A1.w = fmaf(v2, x21.w, A1.w);
        A0.x = fmaf(v3, x30.x, A0.x); A0.y = fmaf(v3, x30.y, A0.y);
        A0.z = fmaf(v3, x30.z, A0.z); A0.w = fmaf(v3, x30.w, A0.w);
        A1.x = fmaf(v3, x31.x, A1.x); A1.y = fmaf(v3, x31.y, A1.y);
        A1.z = fmaf(v3, x31.z, A1.z); A1.w = fmaf(v3, x31.w, A1.w);
    }
    for (; k < cnt; k++) {
        int j  = __ldg(&sidx[(size_t)k * NN + i]);
        float v = __ldg(&sval[(size_t)k * NN + i]);
        float4 x0 = __ldg(&Xin[(size_t)j * FB4 + c0]);
        float4 x1 = __ldg(&Xin[(size_t)j * FB4 + c1]);
        A0.x = fmaf(v, x0.x, A0.x); A0.y = fmaf(v, x0.y, A0.y);
        A0.z = fmaf(v, x0.z, A0.z); A0.w = fmaf(v, x0.w, A0.w);
        A1.x = fmaf(v, x1.x, A1.x); A1.y = fmaf(v, x1.y, A1.y);
        A1.z = fmaf(v, x1.z, A1.z); A1.w = fmaf(v, x1.w, A1.w);
    }
    float4 r0 = make_float4(alpha * A0.x, alpha * A0.y, alpha * A0.z, alpha * A0.w);
    float4 r1 = make_float4(alpha * A1.x, alpha * A1.y, alpha * A1.z, alpha * A1.w);
    if (sub_sel >= 0) {
        const float4* Xs = (const float4*)sel_buf(sub_sel);
        float4 s0 = __ldg(&Xs[(size_t)i * FB4 + c0]);
        float4 s1 = __ldg(&Xs[(size_t)i * FB4 + c1]);
        r0.x -= s0.x; r0.y -= s0.y; r0.z -= s0.z; r0.w -= s0.w;
        r1.x -= s1.x; r1.y -= s1.y; r1.z -= s1.z; r1.w -= s1.w;
    }
    float4* Y = (float4*)sel_buf(out_sel);
    Y[(size_t)i * FB4 + c0] = r0;
    Y[(size_t)i * FB4 + c1] = r1;
}

// ---------------- proj1: tf32 MMA, 128 rows x 128 cols per CTA ------------------
// 8 warps, each warp: 16 rows x 128 cols (16 n8 tiles). K chunked by 24 (3 k8 steps).
__global__ __launch_bounds__(256) void proj1_k(const float* __restrict__ W,
                                               const float* __restrict__ bias,
                                               const float* __restrict__ hx) {
    __shared__ unsigned As[128][28];   // stride 28: conflict-free A frags
    __shared__ unsigned Ws[24][136];   // stride 136 (8 mod 32): conflict-free B frags
    int b = blockIdx.y;
    int n0 = blockIdx.x * 128;
    int t = threadIdx.x;
    int w = t >> 5, lane = t & 31, g = lane >> 2, tig = lane & 3;

    float acc[16][4];
#pragma unroll
    for (int i = 0; i < 16; i++)
#pragma unroll
        for (int q = 0; q < 4; q++) acc[i][q] = 0.f;

    for (int m = 0; m < MM; m++) {
        const float* Am = (m == 0) ? g_X0 : g_M[m - 1];
        for (int ch = 0; ch < 3; ch++) {
            int k0 = ch * 24;
            __syncthreads();
            for (int e = t; e < 128 * 24; e += 256) {
                int r = e / 24, c = e - (e / 24) * 24;
                int f = k0 + c;
                As[r][c] = (f < FF) ? f2tf(Am[(size_t)(n0 + r) * FB + b * FF + f]) : 0u;
            }
            for (int e = t; e < 24 * 128; e += 256) {
                int kk = e >> 7, o = e & 127;
                int f = k0 + kk;
                Ws[kk][o] = (f < FF) ? f2tf(W[(size_t)(f * MM + m) * 128 + o]) : 0u;
            }
            __syncthreads();
#pragma unroll
            for (int ks = 0; ks < 3; ks++) {
                int kc = ks * 8;
                unsigned a[4];
                a[0] = As[w * 16 + g][kc + tig];
                a[1] = As[w * 16 + g + 8][kc + tig];
                a[2] = As[w * 16 + g][kc + tig + 4];
                a[3] = As[w * 16 + g + 8][kc + tig + 4];
#pragma unroll
                for (int tile = 0; tile < 16; tile++) {
                    unsigned b0 = Ws[kc + tig][tile * 8 + g];
                    unsigned b1 = Ws[kc + tig + 4][tile * 8 + g];
                    mma_tf32(acc[tile], a, b0, b1);
                }
            }
        }
    }

#pragma unroll
    for (int tile = 0; tile < 16; tile++) {
        int o0 = tile * 8 + tig * 2;
#pragma unroll
        for (int h = 0; h < 2; h++) {
            int n = n0 + w * 16 + g + h * 8;
#pragma unroll
            for (int q = 0; q < 2; q++) {
                int o = o0 + q;
                float z = acc[tile][h * 2 + q] + bias[o];
                float s = 1.0f / (1.0f + expf(-z));
                if (o < UU) {
                    float hv = hx[(size_t)b * (NN * UU) + (size_t)n * UU + o];
                    g_X2[(size_t)n * FB + b * FF + 2 + o] = s * hv;
                } else {
                    g_U[(size_t)b * (NN * UU) + (size_t)n * UU + (o - UU)] = s;
                }
            }
        }
    }
}

// ---------------- proj2: tf32 MMA, 128 rows x 64 cols per CTA -------------------
__global__ __launch_bounds__(256) void proj2_k(const float* __restrict__ W2,
                                               const float* __restrict__ b2,
                                               const float* __restrict__ hx,
                                               float* __restrict__ out) {
    __shared__ unsigned As[128][28];
    __shared__ unsigned Ws[24][72];    // stride 72 (8 mod 32): conflict-free
    int b = blockIdx.y;
    int n0 = blockIdx.x * 128;
    int t = threadIdx.x;
    int w = t >> 5, lane = t & 31, g = lane >> 2, tig = lane & 3;

    float acc[8][4];
#pragma unroll
    for (int i = 0; i < 8; i++)
#pragma unroll
        for (int q = 0; q < 4; q++) acc[i][q] = 0.f;

    for (int m = 0; m < MM; m++) {
        const float* Am = (m == 0) ? g_X2 : g_M[m - 1];
        for (int ch = 0; ch < 3; ch++) {
            int k0 = ch * 24;
            __syncthreads();
            for (int e = t; e < 128 * 24; e += 256) {
                int r = e / 24, c = e - (e / 24) * 24;
                int f = k0 + c;
                As[r][c] = (f < FF) ? f2tf(Am[(size_t)(n0 + r) * FB + b * FF + f]) : 0u;
            }
            for (int e = t; e < 24 * 64; e += 256) {
                int kk = e >> 6, o = e & 63;
                int f = k0 + kk;
                Ws[kk][o] = (f < FF) ? f2tf(W2[(size_t)(f * MM + m) * 64 + o]) : 0u;
            }
            __syncthreads();
#pragma unroll
            for (int ks = 0; ks < 3; ks++) {
                int kc = ks * 8;
                unsigned a[4];
                a[0] = As[w * 16 + g][kc + tig];
                a[1] = As[w * 16 + g + 8][kc + tig];
                a[2] = As[w * 16 + g][kc + tig + 4];
                a[3] = As[w * 16 + g + 8][kc + tig + 4];
#pragma unroll
                for (int tile = 0; tile < 8; tile++) {
                    unsigned b0 = Ws[kc + tig][tile * 8 + g];
                    unsigned b1 = Ws[kc + tig + 4][tile * 8 + g];
                    mma_tf32(acc[tile], a, b0, b1);
                }
            }
        }
    }

#pragma unroll
    for (int tile = 0; tile < 8; tile++) {
        int o0 = tile * 8 + tig * 2;
#pragma unroll
        for (int h = 0; h < 2; h++) {
            int n = n0 + w * 16 + g + h * 8;
#pragma unroll
            for (int q = 0; q < 2; q++) {
                int o = o0 + q;
                float z = acc[tile][h * 2 + q] + b2[o];
                float c = tanhf(z);
                size_t off = (size_t)b * (NN * UU) + (size_t)n * UU + o;
                float u = g_U[off];
                float hv = hx[off];
                out[off] = u * hv + (1.0f - u) * c;
            }
        }
    }
}

// ---------------- launcher ----------------
extern "C" void kernel_launch(void* const* d_in, const int* in_sizes, int n_in,
                              void* d_out, int out_size) {
    const float* inputs = (const float*)d_in[0];
    const float* hx     = (const float*)d_in[1];
    const float* s0     = (const float*)d_in[2];
    const float* s1     = (const float*)d_in[3];
    const float* W      = (const float*)d_in[4];
    const float* bias   = (const float*)d_in[5];
    const float* W2     = (const float*)d_in[6];
    const float* b2     = (const float*)d_in[7];
    float* out = (float*)d_out;

    build_sparse_k<<<NN / 8, 256>>>(s0, 0);
    build_sparse_k<<<NN / 8, 256>>>(s1, 1);
    build_x_k<<<(NN * FB + 255) / 256, 256>>>(inputs, hx);

    // gconv1
    spmm_k<<<NN, 264>>>(0, 0, -1, 1, 1.0f);  // M0 = S0 @ X0
    spmm_k<<<NN, 264>>>(0, 1,  0, 2, 2.0f);  // M1 = 2*S0 @ M0 - X0
    spmm_k<<<NN, 264>>>(1, 0, -1, 3, 1.0f);  // M2 = S1 @ X0
    spmm_k<<<NN, 264>>>(1, 3,  0, 4, 2.0f);  // M3 = 2*S1 @ M2 - X0

    proj1_k<<<dim3(NN / 128, BB), 256>>>(W, bias, hx);

    // gconv2
    spmm_k<<<NN, 264>>>(0, 5, -1, 1, 1.0f);
    spmm_k<<<NN, 264>>>(0, 1,  5, 2, 2.0f);
    spmm_k<<<NN, 264>>>(1, 5, -1, 3, 1.0f);
    spmm_k<<<NN, 264>>>(1, 3,  5, 4, 2.0f);

    proj2_k<<<dim3(NN / 128, BB), 256>>>(W2, b2, hx, out);
}

// round 8
// speedup vs baseline: 1.3541x; 1.3541x over previous
#include <cuda_runtime.h>
#include <cstdint>
#include <math.h>

#define NN 4096
#define BB 32
#define FF 66
#define UU 64
#define MM 5
#define FB 2112          // FF*BB
#define FB4 528          // FB/4
#define NNZ_MAX 128

// ---------------- scratch ----------------
__device__ float g_X0[(size_t)NN * FB];
__device__ float g_X2[(size_t)NN * FB];
__device__ float g_M[4][(size_t)NN * FB];
__device__ float g_U[(size_t)BB * NN * UU];
__device__ int   g_sidx[2][(size_t)NNZ_MAX * NN];
__device__ float g_sval[2][(size_t)NNZ_MAX * NN];
__device__ int   g_cnt[2][NN];

// ---------------- packed f32x2 helpers ----------------
__device__ __forceinline__ unsigned long long pack2(float lo, float hi) {
    unsigned long long r;
    asm("mov.b64 %0, {%1, %2};" : "=l"(r) : "f"(lo), "f"(hi));
    return r;
}
__device__ __forceinline__ void unpack2(unsigned long long v, float& lo, float& hi) {
    asm("mov.b64 {%0, %1}, %2;" : "=f"(lo), "=f"(hi) : "l"(v));
}
__device__ __forceinline__ void ffma2(unsigned long long& d, unsigned long long a,
                                      unsigned long long b) {
    asm("fma.rn.f32x2 %0, %1, %2, %0;" : "+l"(d) : "l"(a), "l"(b));
}

// ---------------- sparse build ----------------
__global__ void build_sparse_k(const float* __restrict__ S, int sup) {
    int gw   = (blockIdx.x * blockDim.x + threadIdx.x) >> 5;
    int lane = threadIdx.x & 31;
    if (gw >= NN) return;
    const float* row = S + (size_t)gw * NN;
    int* idx = g_sidx[sup];
    float* val = g_sval[sup];
    int c = 0;
    for (int j0 = 0; j0 < NN; j0 += 32) {
        float v = row[j0 + lane];
        unsigned m = __ballot_sync(0xffffffffu, v != 0.0f);
        int pre = __popc(m & ((1u << lane) - 1u));
        if (v != 0.0f) {
            int slot = c + pre;
            if (slot < NNZ_MAX) {
                idx[(size_t)slot * NN + gw] = j0 + lane;
                val[(size_t)slot * NN + gw] = v;
            }
        }
        c += __popc(m);
    }
    if (lane == 0) g_cnt[sup][gw] = (c < NNZ_MAX) ? c : NNZ_MAX;
}

// ---------------- build X0 / static X2 ----------------
__global__ void build_x_k(const float* __restrict__ inp, const float* __restrict__ hx) {
    int e = blockIdx.x * blockDim.x + threadIdx.x;
    if (e >= NN * FB) return;
    int n = e / FB;
    int rem = e - n * FB;
    int b = rem / FF;
    int f = rem - b * FF;
    float v;
    if (f < 2) {
        v = inp[(size_t)b * (NN * 2) + n * 2 + f];
        g_X2[e] = v;
    } else {
        v = hx[(size_t)b * (NN * UU) + (size_t)n * UU + (f - 2)];
    }
    g_X0[e] = v;
}

__device__ __forceinline__ float* sel_buf(int s) {
    if (s == 0) return g_X0;
    if (s == 5) return g_X2;
    return g_M[s - 1];
}

// ---------------- SpMM (R1 proven config) ----------------
__global__ __launch_bounds__(264) void spmm_k(int sup, int in_sel, int sub_sel,
                                              int out_sel, float alpha) {
    int i = blockIdx.y;
    int col = blockIdx.x * 264 + threadIdx.x;  // 0..527
    const float4* __restrict__ Xin = (const float4*)sel_buf(in_sel);
    const int*   __restrict__ sidx = g_sidx[sup];
    const float* __restrict__ sval = g_sval[sup];
    int cnt = g_cnt[sup][i];

    float4 acc = make_float4(0.f, 0.f, 0.f, 0.f);
    int k = 0;
    for (; k + 3 < cnt; k += 4) {
        int j0 = __ldg(&sidx[(size_t)(k + 0) * NN + i]);
        int j1 = __ldg(&sidx[(size_t)(k + 1) * NN + i]);
        int j2 = __ldg(&sidx[(size_t)(k + 2) * NN + i]);
        int j3 = __ldg(&sidx[(size_t)(k + 3) * NN + i]);
        float v0 = __ldg(&sval[(size_t)(k + 0) * NN + i]);
        float v1 = __ldg(&sval[(size_t)(k + 1) * NN + i]);
        float v2 = __ldg(&sval[(size_t)(k + 2) * NN + i]);
        float v3 = __ldg(&sval[(size_t)(k + 3) * NN + i]);
        float4 x0 = __ldg(&Xin[(size_t)j0 * FB4 + col]);
        float4 x1 = __ldg(&Xin[(size_t)j1 * FB4 + col]);
        float4 x2 = __ldg(&Xin[(size_t)j2 * FB4 + col]);
        float4 x3 = __ldg(&Xin[(size_t)j3 * FB4 + col]);
        acc.x = fmaf(v0, x0.x, acc.x); acc.y = fmaf(v0, x0.y, acc.y);
        acc.z = fmaf(v0, x0.z, acc.z); acc.w = fmaf(v0, x0.w, acc.w);
        acc.x = fmaf(v1, x1.x, acc.x); acc.y = fmaf(v1, x1.y, acc.y);
        acc.z = fmaf(v1, x1.z, acc.z); acc.w = fmaf(v1, x1.w, acc.w);
        acc.x = fmaf(v2, x2.x, acc.x); acc.y = fmaf(v2, x2.y, acc.y);
        acc.z = fmaf(v2, x2.z, acc.z); acc.w = fmaf(v2, x2.w, acc.w);
        acc.x = fmaf(v3, x3.x, acc.x); acc.y = fmaf(v3, x3.y, acc.y);
        acc.z = fmaf(v3, x3.z, acc.z); acc.w = fmaf(v3, x3.w, acc.w);
    }
    for (; k < cnt; k++) {
        int j  = __ldg(&sidx[(size_t)k * NN + i]);
        float v = __ldg(&sval[(size_t)k * NN + i]);
        float4 x = __ldg(&Xin[(size_t)j * FB4 + col]);
        acc.x = fmaf(v, x.x, acc.x); acc.y = fmaf(v, x.y, acc.y);
        acc.z = fmaf(v, x.z, acc.z); acc.w = fmaf(v, x.w, acc.w);
    }
    float4 r = make_float4(alpha * acc.x, alpha * acc.y, alpha * acc.z, alpha * acc.w);
    if (sub_sel >= 0) {
        const float4* Xs = (const float4*)sel_buf(sub_sel);
        float4 s = Xs[(size_t)i * FB4 + col];
        r.x -= s.x; r.y -= s.y; r.z -= s.z; r.w -= s.w;
    }
    ((float4*)sel_buf(out_sel))[(size_t)i * FB4 + col] = r;
}

// ---------------- proj1: f32x2 FFMA2 GEMM, 64 rows x 128 cols per CTA ----------
// 256 threads: tx = t&15 owns cols [tx*8, tx*8+8) (4 f32x2 pairs); ty = t>>4 owns
// rows ty, ty+16, ty+32, ty+48.
__global__ __launch_bounds__(256) void proj1_k(const float* __restrict__ W,
                                               const float* __restrict__ bias,
                                               const float* __restrict__ hx) {
    __shared__ float As[64][68];
    __shared__ float Ws[66][128];
    int b = blockIdx.y;
    int n0 = blockIdx.x * 64;
    int t = threadIdx.x;
    int tx = t & 15, ty = t >> 4;

    unsigned long long acc[4][4];
#pragma unroll
    for (int rr = 0; rr < 4; rr++)
#pragma unroll
        for (int q = 0; q < 4; q++) acc[rr][q] = 0ULL;

#pragma unroll 1
    for (int m = 0; m < MM; m++) {
        const float* Am = (m == 0) ? g_X0 : g_M[m - 1];
        for (int e = t; e < 64 * FF; e += 256) {
            int r = e / FF, f = e - r * FF;
            As[r][f] = Am[(size_t)(n0 + r) * FB + b * FF + f];
        }
        for (int e = t; e < FF * 128; e += 256) {
            int f = e >> 7, o = e & 127;
            Ws[f][o] = W[(size_t)(f * MM + m) * 128 + o];
        }
        __syncthreads();
#pragma unroll 6
        for (int kk = 0; kk < FF; kk++) {
            unsigned long long a2[4];
#pragma unroll
            for (int rr = 0; rr < 4; rr++) {
                float a = As[ty + 16 * rr][kk];
                a2[rr] = pack2(a, a);
            }
            unsigned long long w2[4];
#pragma unroll
            for (int q = 0; q < 4; q++)
                w2[q] = *(const unsigned long long*)&Ws[kk][tx * 8 + q * 2];
#pragma unroll
            for (int rr = 0; rr < 4; rr++)
#pragma unroll
                for (int q = 0; q < 4; q++)
                    ffma2(acc[rr][q], a2[rr], w2[q]);
        }
        __syncthreads();
    }

#pragma unroll
    for (int rr = 0; rr < 4; rr++) {
        int n = n0 + ty + 16 * rr;
#pragma unroll
        for (int q = 0; q < 4; q++) {
            float z0, z1;
            unpack2(acc[rr][q], z0, z1);
#pragma unroll
            for (int h = 0; h < 2; h++) {
                int o = tx * 8 + q * 2 + h;
                float z = (h == 0 ? z0 : z1) + bias[o];
                float s = 1.0f / (1.0f + expf(-z));
                if (o < UU) {
                    float hv = hx[(size_t)b * (NN * UU) + (size_t)n * UU + o];
                    g_X2[(size_t)n * FB + b * FF + 2 + o] = s * hv;
                } else {
                    g_U[(size_t)b * (NN * UU) + (size_t)n * UU + (o - UU)] = s;
                }
            }
        }
    }
}

// ---------------- proj2: f32x2 FFMA2 GEMM, 64 rows x 64 cols per CTA -----------
// tx owns cols [tx*4, tx*4+4) (2 f32x2 pairs).
__global__ __launch_bounds__(256) void proj2_k(const float* __restrict__ W2,
                                               const float* __restrict__ b2,
                                               const float* __restrict__ hx,
                                               float* __restrict__ out) {
    __shared__ float As[64][68];
    __shared__ float Ws[66][64];
    int b = blockIdx.y;
    int n0 = blockIdx.x * 64;
    int t = threadIdx.x;
    int tx = t & 15, ty = t >> 4;

    unsigned long long acc[4][2];
#pragma unroll
    for (int rr = 0; rr < 4; rr++)
#pragma unroll
        for (int q = 0; q < 2; q++) acc[rr][q] = 0ULL;

#pragma unroll 1
    for (int m = 0; m < MM; m++) {
        const float* Am = (m == 0) ? g_X2 : g_M[m - 1];
        for (int e = t; e < 64 * FF; e += 256) {
            int r = e / FF, f = e - r * FF;
            As[r][f] = Am[(size_t)(n0 + r) * FB + b * FF + f];
        }
        for (int e = t; e < FF * 64; e += 256) {
            int f = e >> 6, o = e & 63;
            Ws[f][o] = W2[(size_t)(f * MM + m) * 64 + o];
        }
        __syncthreads();
#pragma unroll 6
        for (int kk = 0; kk < FF; kk++) {
            unsigned long long a2[4];
#pragma unroll
            for (int rr = 0; rr < 4; rr++) {
                float a = As[ty + 16 * rr][kk];
                a2[rr] = pack2(a, a);
            }
            unsigned long long w2[2];
#pragma unroll
            for (int q = 0; q < 2; q++)
                w2[q] = *(const unsigned long long*)&Ws[kk][tx * 4 + q * 2];
#pragma unroll
            for (int rr = 0; rr < 4; rr++)
#pragma unroll
                for (int q = 0; q < 2; q++)
                    ffma2(acc[rr][q], a2[rr], w2[q]);
        }
        __syncthreads();
    }

#pragma unroll
    for (int rr = 0; rr < 4; rr++) {
        int n = n0 + ty + 16 * rr;
#pragma unroll
        for (int q = 0; q < 2; q++) {
            float z0, z1;
            unpack2(acc[rr][q], z0, z1);
#pragma unroll
            for (int h = 0; h < 2; h++) {
                int o = tx * 4 + q * 2 + h;
                float z = (h == 0 ? z0 : z1) + b2[o];
                float c = tanhf(z);
                size_t off = (size_t)b * (NN * UU) + (size_t)n * UU + o;
                float u = g_U[off];
                float hv = hx[off];
                out[off] = u * hv + (1.0f - u) * c;
            }
        }
    }
}

// ---------------- launcher ----------------
extern "C" void kernel_launch(void* const* d_in, const int* in_sizes, int n_in,
                              void* d_out, int out_size) {
    const float* inputs = (const float*)d_in[0];
    const float* hx     = (const float*)d_in[1];
    const float* s0     = (const float*)d_in[2];
    const float* s1     = (const float*)d_in[3];
    const float* W      = (const float*)d_in[4];
    const float* bias   = (const float*)d_in[5];
    const float* W2     = (const float*)d_in[6];
    const float* b2     = (const float*)d_in[7];
    float* out = (float*)d_out;

    build_sparse_k<<<NN / 8, 256>>>(s0, 0);
    build_sparse_k<<<NN / 8, 256>>>(s1, 1);
    build_x_k<<<(NN * FB + 255) / 256, 256>>>(inputs, hx);

    dim3 sgrid(2, NN);
    // gconv1
    spmm_k<<<sgrid, 264>>>(0, 0, -1, 1, 1.0f);  // M0 = S0 @ X0
    spmm_k<<<sgrid, 264>>>(0, 1,  0, 2, 2.0f);  // M1 = 2*S0 @ M0 - X0
    spmm_k<<<sgrid, 264>>>(1, 0, -1, 3, 1.0f);  // M2 = S1 @ X0
    spmm_k<<<sgrid, 264>>>(1, 3,  0, 4, 2.0f);  // M3 = 2*S1 @ M2 - X0

    proj1_k<<<dim3(NN / 64, BB), 256>>>(W, bias, hx);

    // gconv2
    spmm_k<<<sgrid, 264>>>(0, 5, -1, 1, 1.0f);
    spmm_k<<<sgrid, 264>>>(0, 1,  5, 2, 2.0f);
    spmm_k<<<sgrid, 264>>>(1, 5, -1, 3, 1.0f);
    spmm_k<<<sgrid, 264>>>(1, 3,  5, 4, 2.0f);

    proj2_k<<<dim3(NN / 64, BB), 256>>>(W2, b2, hx, out);
}

// round 9
// speedup vs baseline: 1.5103x; 1.1153x over previous
#include <cuda_runtime.h>
#include <cstdint>
#include <math.h>

#define NN 4096
#define BB 32
#define FF 66
#define UU 64
#define MM 5
#define FB 2112          // FF*BB
#define FB4 528          // FB/4
#define NNZ_MAX 128

// ---------------- scratch ----------------
__device__ float g_X0[(size_t)NN * FB];
__device__ float g_X2[(size_t)NN * FB];
__device__ float g_M[4][(size_t)NN * FB];
__device__ float g_U[(size_t)BB * NN * UU];
__device__ int   g_sidx[2][(size_t)NNZ_MAX * NN];
__device__ float g_sval[2][(size_t)NNZ_MAX * NN];
__device__ int   g_cnt[2][NN];

// ---------------- packed f32x2 helpers ----------------
__device__ __forceinline__ unsigned long long pack2(float lo, float hi) {
    unsigned long long r;
    asm("mov.b64 %0, {%1, %2};" : "=l"(r) : "f"(lo), "f"(hi));
    return r;
}
__device__ __forceinline__ void unpack2(unsigned long long v, float& lo, float& hi) {
    asm("mov.b64 {%0, %1}, %2;" : "=f"(lo), "=f"(hi) : "l"(v));
}
__device__ __forceinline__ void ffma2(unsigned long long& d, unsigned long long a,
                                      unsigned long long b) {
    asm("fma.rn.f32x2 %0, %1, %2, %0;" : "+l"(d) : "l"(a), "l"(b));
}

// ---------------- sparse build ----------------
__global__ void build_sparse_k(const float* __restrict__ S, int sup) {
    int gw   = (blockIdx.x * blockDim.x + threadIdx.x) >> 5;
    int lane = threadIdx.x & 31;
    if (gw >= NN) return;
    const float* row = S + (size_t)gw * NN;
    int* idx = g_sidx[sup];
    float* val = g_sval[sup];
    int c = 0;
    for (int j0 = 0; j0 < NN; j0 += 32) {
        float v = row[j0 + lane];
        unsigned m = __ballot_sync(0xffffffffu, v != 0.0f);
        int pre = __popc(m & ((1u << lane) - 1u));
        if (v != 0.0f) {
            int slot = c + pre;
            if (slot < NNZ_MAX) {
                idx[(size_t)slot * NN + gw] = j0 + lane;
                val[(size_t)slot * NN + gw] = v;
            }
        }
        c += __popc(m);
    }
    if (lane == 0) g_cnt[sup][gw] = (c < NNZ_MAX) ? c : NNZ_MAX;
}

// ---------------- build X0 / static X2 ----------------
__global__ void build_x_k(const float* __restrict__ inp, const float* __restrict__ hx) {
    int e = blockIdx.x * blockDim.x + threadIdx.x;
    if (e >= NN * FB) return;
    int n = e / FB;
    int rem = e - n * FB;
    int b = rem / FF;
    int f = rem - b * FF;
    float v;
    if (f < 2) {
        v = inp[(size_t)b * (NN * 2) + n * 2 + f];
        g_X2[e] = v;
    } else {
        v = hx[(size_t)b * (NN * UU) + (size_t)n * UU + (f - 2)];
    }
    g_X0[e] = v;
}

__device__ __forceinline__ float* sel_buf(int s) {
    if (s == 0) return g_X0;
    if (s == 5) return g_X2;
    return g_M[s - 1];
}

// ---------------- SpMM (R1 proven config) ----------------
__global__ __launch_bounds__(264) void spmm_k(int sup, int in_sel, int sub_sel,
                                              int out_sel, float alpha) {
    int i = blockIdx.y;
    int col = blockIdx.x * 264 + threadIdx.x;  // 0..527
    const float4* __restrict__ Xin = (const float4*)sel_buf(in_sel);
    const int*   __restrict__ sidx = g_sidx[sup];
    const float* __restrict__ sval = g_sval[sup];
    int cnt = g_cnt[sup][i];

    float4 acc = make_float4(0.f, 0.f, 0.f, 0.f);
    int k = 0;
    for (; k + 3 < cnt; k += 4) {
        int j0 = __ldg(&sidx[(size_t)(k + 0) * NN + i]);
        int j1 = __ldg(&sidx[(size_t)(k + 1) * NN + i]);
        int j2 = __ldg(&sidx[(size_t)(k + 2) * NN + i]);
        int j3 = __ldg(&sidx[(size_t)(k + 3) * NN + i]);
        float v0 = __ldg(&sval[(size_t)(k + 0) * NN + i]);
        float v1 = __ldg(&sval[(size_t)(k + 1) * NN + i]);
        float v2 = __ldg(&sval[(size_t)(k + 2) * NN + i]);
        float v3 = __ldg(&sval[(size_t)(k + 3) * NN + i]);
        float4 x0 = __ldg(&Xin[(size_t)j0 * FB4 + col]);
        float4 x1 = __ldg(&Xin[(size_t)j1 * FB4 + col]);
        float4 x2 = __ldg(&Xin[(size_t)j2 * FB4 + col]);
        float4 x3 = __ldg(&Xin[(size_t)j3 * FB4 + col]);
        acc.x = fmaf(v0, x0.x, acc.x); acc.y = fmaf(v0, x0.y, acc.y);
        acc.z = fmaf(v0, x0.z, acc.z); acc.w = fmaf(v0, x0.w, acc.w);
        acc.x = fmaf(v1, x1.x, acc.x); acc.y = fmaf(v1, x1.y, acc.y);
        acc.z = fmaf(v1, x1.z, acc.z); acc.w = fmaf(v1, x1.w, acc.w);
        acc.x = fmaf(v2, x2.x, acc.x); acc.y = fmaf(v2, x2.y, acc.y);
        acc.z = fmaf(v2, x2.z, acc.z); acc.w = fmaf(v2, x2.w, acc.w);
        acc.x = fmaf(v3, x3.x, acc.x); acc.y = fmaf(v3, x3.y, acc.y);
        acc.z = fmaf(v3, x3.z, acc.z); acc.w = fmaf(v3, x3.w, acc.w);
    }
    for (; k < cnt; k++) {
        int j  = __ldg(&sidx[(size_t)k * NN + i]);
        float v = __ldg(&sval[(size_t)k * NN + i]);
        float4 x = __ldg(&Xin[(size_t)j * FB4 + col]);
        acc.x = fmaf(v, x.x, acc.x); acc.y = fmaf(v, x.y, acc.y);
        acc.z = fmaf(v, x.z, acc.z); acc.w = fmaf(v, x.w, acc.w);
    }
    float4 r = make_float4(alpha * acc.x, alpha * acc.y, alpha * acc.z, alpha * acc.w);
    if (sub_sel >= 0) {
        const float4* Xs = (const float4*)sel_buf(sub_sel);
        float4 s = Xs[(size_t)i * FB4 + col];
        r.x -= s.x; r.y -= s.y; r.z -= s.z; r.w -= s.w;
    }
    ((float4*)sel_buf(out_sel))[(size_t)i * FB4 + col] = r;
}

// ---------------- proj1: FFMA2 GEMM, 64 rows x 128 cols per CTA ----------------
// 256 threads: tx = t&15 owns col pairs {tx*2 + q*32} (q=0..3) -> LDS.64 across tx
// is 8B-strided (conflict-free). ty = t>>4 owns rows ty, ty+16, ty+32, ty+48.
__global__ __launch_bounds__(256) void proj1_k(const float* __restrict__ W,
                                               const float* __restrict__ bias,
                                               const float* __restrict__ hx) {
    __shared__ float As[64][68];
    __shared__ float Ws[66][128];
    int b = blockIdx.y;
    int n0 = blockIdx.x * 64;
    int t = threadIdx.x;
    int tx = t & 15, ty = t >> 4;

    unsigned long long acc[4][4];
#pragma unroll
    for (int rr = 0; rr < 4; rr++)
#pragma unroll
        for (int q = 0; q < 4; q++) acc[rr][q] = 0ULL;

#pragma unroll 1
    for (int m = 0; m < MM; m++) {
        const float* Am = (m == 0) ? g_X0 : g_M[m - 1];
        for (int e = t; e < 64 * FF; e += 256) {
            int r = e / FF, f = e - r * FF;
            As[r][f] = Am[(size_t)(n0 + r) * FB + b * FF + f];
        }
        for (int e = t; e < FF * 128; e += 256) {
            int f = e >> 7, o = e & 127;
            Ws[f][o] = W[(size_t)(f * MM + m) * 128 + o];
        }
        __syncthreads();
#pragma unroll 6
        for (int kk = 0; kk < FF; kk++) {
            unsigned long long a2[4];
#pragma unroll
            for (int rr = 0; rr < 4; rr++) {
                float a = As[ty + 16 * rr][kk];
                a2[rr] = pack2(a, a);
            }
            unsigned long long w2[4];
#pragma unroll
            for (int q = 0; q < 4; q++)
                w2[q] = *(const unsigned long long*)&Ws[kk][q * 32 + tx * 2];
#pragma unroll
            for (int rr = 0; rr < 4; rr++)
#pragma unroll
                for (int q = 0; q < 4; q++)
                    ffma2(acc[rr][q], a2[rr], w2[q]);
        }
        __syncthreads();
    }

#pragma unroll
    for (int rr = 0; rr < 4; rr++) {
        int n = n0 + ty + 16 * rr;
#pragma unroll
        for (int q = 0; q < 4; q++) {
            float z0, z1;
            unpack2(acc[rr][q], z0, z1);
#pragma unroll
            for (int h = 0; h < 2; h++) {
                int o = q * 32 + tx * 2 + h;
                float z = (h == 0 ? z0 : z1) + bias[o];
                float s = 1.0f / (1.0f + expf(-z));
                if (o < UU) {
                    float hv = hx[(size_t)b * (NN * UU) + (size_t)n * UU + o];
                    g_X2[(size_t)n * FB + b * FF + 2 + o] = s * hv;
                } else {
                    g_U[(size_t)b * (NN * UU) + (size_t)n * UU + (o - UU)] = s;
                }
            }
        }
    }
}

// ---------------- proj2: FFMA2 GEMM, 64 rows x 64 cols per CTA -----------------
// tx owns col pairs {tx*2 + q*32} (q=0..1).
__global__ __launch_bounds__(256) void proj2_k(const float* __restrict__ W2,
                                               const float* __restrict__ b2,
                                               const float* __restrict__ hx,
                                               float* __restrict__ out) {
    __shared__ float As[64][68];
    __shared__ float Ws[66][64];
    int b = blockIdx.y;
    int n0 = blockIdx.x * 64;
    int t = threadIdx.x;
    int tx = t & 15, ty = t >> 4;

    unsigned long long acc[4][2];
#pragma unroll
    for (int rr = 0; rr < 4; rr++)
#pragma unroll
        for (int q = 0; q < 2; q++) acc[rr][q] = 0ULL;

#pragma unroll 1
    for (int m = 0; m < MM; m++) {
        const float* Am = (m == 0) ? g_X2 : g_M[m - 1];
        for (int e = t; e < 64 * FF; e += 256) {
            int r = e / FF, f = e - r * FF;
            As[r][f] = Am[(size_t)(n0 + r) * FB + b * FF + f];
        }
        for (int e = t; e < FF * 64; e += 256) {
            int f = e >> 6, o = e & 63;
            Ws[f][o] = W2[(size_t)(f * MM + m) * 64 + o];
        }
        __syncthreads();
#pragma unroll 6
        for (int kk = 0; kk < FF; kk++) {
            unsigned long long a2[4];
#pragma unroll
            for (int rr = 0; rr < 4; rr++) {
                float a = As[ty + 16 * rr][kk];
                a2[rr] = pack2(a, a);
            }
            unsigned long long w2[2];
#pragma unroll
            for (int q = 0; q < 2; q++)
                w2[q] = *(const unsigned long long*)&Ws[kk][q * 32 + tx * 2];
#pragma unroll
            for (int rr = 0; rr < 4; rr++)
#pragma unroll
                for (int q = 0; q < 2; q++)
                    ffma2(acc[rr][q], a2[rr], w2[q]);
        }
        __syncthreads();
    }

#pragma unroll
    for (int rr = 0; rr < 4; rr++) {
        int n = n0 + ty + 16 * rr;
#pragma unroll
        for (int q = 0; q < 2; q++) {
            float z0, z1;
            unpack2(acc[rr][q], z0, z1);
#pragma unroll
            for (int h = 0; h < 2; h++) {
                int o = q * 32 + tx * 2 + h;
                float z = (h == 0 ? z0 : z1) + b2[o];
                float c = tanhf(z);
                size_t off = (size_t)b * (NN * UU) + (size_t)n * UU + o;
                float u = g_U[off];
                float hv = hx[off];
                out[off] = u * hv + (1.0f - u) * c;
            }
        }
    }
}

// ---------------- launcher ----------------
extern "C" void kernel_launch(void* const* d_in, const int* in_sizes, int n_in,
                              void* d_out, int out_size) {
    const float* inputs = (const float*)d_in[0];
    const float* hx     = (const float*)d_in[1];
    const float* s0     = (const float*)d_in[2];
    const float* s1     = (const float*)d_in[3];
    const float* W      = (const float*)d_in[4];
    const float* bias   = (const float*)d_in[5];
    const float* W2     = (const float*)d_in[6];
    const float* b2     = (const float*)d_in[7];
    float* out = (float*)d_out;

    build_sparse_k<<<NN / 8, 256>>>(s0, 0);
    build_sparse_k<<<NN / 8, 256>>>(s1, 1);
    build_x_k<<<(NN * FB + 255) / 256, 256>>>(inputs, hx);

    dim3 sgrid(2, NN);
    // gconv1
    spmm_k<<<sgrid, 264>>>(0, 0, -1, 1, 1.0f);  // M0 = S0 @ X0
    spmm_k<<<sgrid, 264>>>(0, 1,  0, 2, 2.0f);  // M1 = 2*S0 @ M0 - X0
    spmm_k<<<sgrid, 264>>>(1, 0, -1, 3, 1.0f);  // M2 = S1 @ X0
    spmm_k<<<sgrid, 264>>>(1, 3,  0, 4, 2.0f);  // M3 = 2*S1 @ M2 - X0

    proj1_k<<<dim3(NN / 64, BB), 256>>>(W, bias, hx);

    // gconv2
    spmm_k<<<sgrid, 264>>>(0, 5, -1, 1, 1.0f);
    spmm_k<<<sgrid, 264>>>(0, 1,  5, 2, 2.0f);
    spmm_k<<<sgrid, 264>>>(1, 5, -1, 3, 1.0f);
    spmm_k<<<sgrid, 264>>>(1, 3,  5, 4, 2.0f);

    proj2_k<<<dim3(NN / 64, BB), 256>>>(W2, b2, hx, out);
}

// round 13
// speedup vs baseline: 1.9066x; 1.2625x over previous
#include <cuda_runtime.h>
#include <cuda_bf16.h>
#include <cstdint>
#include <math.h>

#define NN 4096
#define BB 32
#define FF 66
#define UU 64
#define MM 5
#define FB 2112          // FF*BB
#define FBQ 264          // FB/8 uint4 (8 bf16) per row
#define NNZ_MAX 128

// ---------------- scratch (bf16 X buffers as uint4 for aligned 16B access) -----
__device__ uint4 g_X0b[(size_t)NN * FBQ];
__device__ uint4 g_X2b[(size_t)NN * FBQ];
__device__ uint4 g_Mb[4][(size_t)NN * FBQ];
__device__ float g_U[(size_t)BB * NN * UU];
__device__ int   g_sidx[2][(size_t)NNZ_MAX * NN];
__device__ float g_sval[2][(size_t)NNZ_MAX * NN];
__device__ int   g_cnt[2][NN];

// ---------------- packed f32x2 helpers ----------------
__device__ __forceinline__ unsigned long long pack2(float lo, float hi) {
    unsigned long long r;
    asm("mov.b64 %0, {%1, %2};" : "=l"(r) : "f"(lo), "f"(hi));
    return r;
}
__device__ __forceinline__ void unpack2(unsigned long long v, float& lo, float& hi) {
    asm("mov.b64 {%0, %1}, %2;" : "=f"(lo), "=f"(hi) : "l"(v));
}
__device__ __forceinline__ void ffma2(unsigned long long& d, unsigned long long a,
                                      unsigned long long b) {
    asm("fma.rn.f32x2 %0, %1, %2, %0;" : "+l"(d) : "l"(a), "l"(b));
}

// ---------------- sparse build ----------------
__global__ void build_sparse_k(const float* __restrict__ S, int sup) {
    int gw   = (blockIdx.x * blockDim.x + threadIdx.x) >> 5;
    int lane = threadIdx.x & 31;
    if (gw >= NN) return;
    const float* row = S + (size_t)gw * NN;
    int* idx = g_sidx[sup];
    float* val = g_sval[sup];
    int c = 0;
    for (int j0 = 0; j0 < NN; j0 += 32) {
        float v = row[j0 + lane];
        unsigned m = __ballot_sync(0xffffffffu, v != 0.0f);
        int pre = __popc(m & ((1u << lane) - 1u));
        if (v != 0.0f) {
            int slot = c + pre;
            if (slot < NNZ_MAX) {
                idx[(size_t)slot * NN + gw] = j0 + lane;
                val[(size_t)slot * NN + gw] = v;
            }
        }
        c += __popc(m);
    }
    if (lane == 0) g_cnt[sup][gw] = (c < NNZ_MAX) ? c : NNZ_MAX;
}

// ---------------- build X0 / static X2 (bf16) ----------------
__global__ void build_x_k(const float* __restrict__ inp, const float* __restrict__ hx) {
    int e = blockIdx.x * blockDim.x + threadIdx.x;
    if (e >= NN * FB) return;
    int n = e / FB;
    int rem = e - n * FB;
    int b = rem / FF;
    int f = rem - b * FF;
    __nv_bfloat16* X0 = (__nv_bfloat16*)g_X0b;
    __nv_bfloat16* X2 = (__nv_bfloat16*)g_X2b;
    float v;
    if (f < 2) {
        v = inp[(size_t)b * (NN * 2) + n * 2 + f];
        X2[e] = __float2bfloat16(v);
    } else {
        v = hx[(size_t)b * (NN * UU) + (size_t)n * UU + (f - 2)];
    }
    X0[e] = __float2bfloat16(v);
}

__device__ __forceinline__ uint4* sel_buf(int s) {
    if (s == 0) return g_X0b;
    if (s == 5) return g_X2b;
    return g_Mb[s - 1];
}

// ---------------- SpMM bf16: 1 row per CTA, 8 bf16 cols/thread, unroll 4 -------
__device__ __forceinline__ void fma8(float* acc, uint4 x, float v) {
    const __nv_bfloat162* p = (const __nv_bfloat162*)&x;
#pragma unroll
    for (int q = 0; q < 4; q++) {
        float2 f = __bfloat1622float2(p[q]);
        acc[2 * q]     = fmaf(v, f.x, acc[2 * q]);
        acc[2 * q + 1] = fmaf(v, f.y, acc[2 * q + 1]);
    }
}

__global__ __launch_bounds__(264) void spmm_k(int sup, int in_sel, int sub_sel,
                                              int out_sel, float alpha) {
    int i = blockIdx.x;
    int t = threadIdx.x;  // 0..263, one uint4 (8 bf16) per thread = full row
    const uint4* __restrict__ Xin = sel_buf(in_sel);
    const int*   __restrict__ sidx = g_sidx[sup];
    const float* __restrict__ sval = g_sval[sup];
    int cnt = g_cnt[sup][i];

    float acc[8];
#pragma unroll
    for (int q = 0; q < 8; q++) acc[q] = 0.f;

    int k = 0;
    for (; k + 3 < cnt; k += 4) {
        int j0 = __ldg(&sidx[(size_t)(k + 0) * NN + i]);
        int j1 = __ldg(&sidx[(size_t)(k + 1) * NN + i]);
        int j2 = __ldg(&sidx[(size_t)(k + 2) * NN + i]);
        int j3 = __ldg(&sidx[(size_t)(k + 3) * NN + i]);
        float v0 = __ldg(&sval[(size_t)(k + 0) * NN + i]);
        float v1 = __ldg(&sval[(size_t)(k + 1) * NN + i]);
        float v2 = __ldg(&sval[(size_t)(k + 2) * NN + i]);
        float v3 = __ldg(&sval[(size_t)(k + 3) * NN + i]);
        uint4 x0 = __ldg(&Xin[(size_t)j0 * FBQ + t]);
        uint4 x1 = __ldg(&Xin[(size_t)j1 * FBQ + t]);
        uint4 x2 = __ldg(&Xin[(size_t)j2 * FBQ + t]);
        uint4 x3 = __ldg(&Xin[(size_t)j3 * FBQ + t]);
        fma8(acc, x0, v0);
        fma8(acc, x1, v1);
        fma8(acc, x2, v2);
        fma8(acc, x3, v3);
    }
    for (; k < cnt; k++) {
        int j  = __ldg(&sidx[(size_t)k * NN + i]);
        float v = __ldg(&sval[(size_t)k * NN + i]);
        uint4 x = __ldg(&Xin[(size_t)j * FBQ + t]);
        fma8(acc, x, v);
    }

    float r[8];
#pragma unroll
    for (int q = 0; q < 8; q++) r[q] = alpha * acc[q];
    if (sub_sel >= 0) {
        const uint4* Xs = sel_buf(sub_sel);
        uint4 s = __ldg(&Xs[(size_t)i * FBQ + t]);
        const __nv_bfloat162* ps = (const __nv_bfloat162*)&s;
#pragma unroll
        for (int q = 0; q < 4; q++) {
            float2 f = __bfloat1622float2(ps[q]);
            r[2 * q]     -= f.x;
            r[2 * q + 1] -= f.y;
        }
    }
    uint4 o;
    __nv_bfloat162* po = (__nv_bfloat162*)&o;
#pragma unroll
    for (int q = 0; q < 4; q++)
        po[q] = __floats2bfloat162_rn(r[2 * q], r[2 * q + 1]);
    sel_buf(out_sel)[(size_t)i * FBQ + t] = o;
}

// ---------------- proj1: FFMA2 GEMM, 64 rows x 128 cols per CTA ----------------
// A staged from bf16 buffers (convert to fp32 in smem); math unchanged from R9.
__global__ __launch_bounds__(256) void proj1_k(const float* __restrict__ W,
                                               const float* __restrict__ bias,
                                               const float* __restrict__ hx) {
    __shared__ float As[64][68];
    __shared__ float Ws[66][128];
    int b = blockIdx.y;
    int n0 = blockIdx.x * 64;
    int t = threadIdx.x;
    int tx = t & 15, ty = t >> 4;

    unsigned long long acc[4][4];
#pragma unroll
    for (int rr = 0; rr < 4; rr++)
#pragma unroll
        for (int q = 0; q < 4; q++) acc[rr][q] = 0ULL;

#pragma unroll 1
    for (int m = 0; m < MM; m++) {
        const __nv_bfloat16* Am = (const __nv_bfloat16*)((m == 0) ? g_X0b : g_Mb[m - 1]);
        for (int e = t; e < 64 * FF; e += 256) {
            int r = e / FF, f = e - r * FF;
            As[r][f] = __bfloat162float(Am[(size_t)(n0 + r) * FB + b * FF + f]);
        }
        for (int e = t; e < FF * 128; e += 256) {
            int f = e >> 7, o = e & 127;
            Ws[f][o] = W[(size_t)(f * MM + m) * 128 + o];
        }
        __syncthreads();
#pragma unroll 6
        for (int kk = 0; kk < FF; kk++) {
            unsigned long long a2[4];
#pragma unroll
            for (int rr = 0; rr < 4; rr++) {
                float a = As[ty + 16 * rr][kk];
                a2[rr] = pack2(a, a);
            }
            unsigned long long w2[4];
#pragma unroll
            for (int q = 0; q < 4; q++)
                w2[q] = *(const unsigned long long*)&Ws[kk][q * 32 + tx * 2];
#pragma unroll
            for (int rr = 0; rr < 4; rr++)
#pragma unroll
                for (int q = 0; q < 4; q++)
                    ffma2(acc[rr][q], a2[rr], w2[q]);
        }
        __syncthreads();
    }

    __nv_bfloat16* X2 = (__nv_bfloat16*)g_X2b;
#pragma unroll
    for (int rr = 0; rr < 4; rr++) {
        int n = n0 + ty + 16 * rr;
#pragma unroll
        for (int q = 0; q < 4; q++) {
            float z0, z1;
            unpack2(acc[rr][q], z0, z1);
#pragma unroll
            for (int h = 0; h < 2; h++) {
                int o = q * 32 + tx * 2 + h;
                float z = (h == 0 ? z0 : z1) + bias[o];
                float s = 1.0f / (1.0f + expf(-z));
                if (o < UU) {
                    float hv = hx[(size_t)b * (NN * UU) + (size_t)n * UU + o];
                    X2[(size_t)n * FB + b * FF + 2 + o] = __float2bfloat16(s * hv);
                } else {
                    g_U[(size_t)b * (NN * UU) + (size_t)n * UU + (o - UU)] = s;
                }
            }
        }
    }
}

// ---------------- proj2: FFMA2 GEMM, 64 rows x 64 cols per CTA -----------------
__global__ __launch_bounds__(256) void proj2_k(const float* __restrict__ W2,
                                               const float* __restrict__ b2,
                                               const float* __restrict__ hx,
                                               float* __restrict__ out) {
    __shared__ float As[64][68];
    __shared__ float Ws[66][64];
    int b = blockIdx.y;
    int n0 = blockIdx.x * 64;
    int t = threadIdx.x;
    int tx = t & 15, ty = t >> 4;

    unsigned long long acc[4][2];
#pragma unroll
    for (int rr = 0; rr < 4; rr++)
#pragma unroll
        for (int q = 0; q < 2; q++) acc[rr][q] = 0ULL;

#pragma unroll 1
    for (int m = 0; m < MM; m++) {
        const __nv_bfloat16* Am = (const __nv_bfloat16*)((m == 0) ? g_X2b : g_Mb[m - 1]);
        for (int e = t; e < 64 * FF; e += 256) {
            int r = e / FF, f = e - r * FF;
            As[r][f] = __bfloat162float(Am[(size_t)(n0 + r) * FB + b * FF + f]);
        }
        for (int e = t; e < FF * 64; e += 256) {
            int f = e >> 6, o = e & 63;
            Ws[f][o] = W2[(size_t)(f * MM + m) * 64 + o];
        }
        __syncthreads();
#pragma unroll 6
        for (int kk = 0; kk < FF; kk++) {
            unsigned long long a2[4];
#pragma unroll
            for (int rr = 0; rr < 4; rr++) {
                float a = As[ty + 16 * rr][kk];
                a2[rr] = pack2(a, a);
            }
            unsigned long long w2[2];
#pragma unroll
            for (int q = 0; q < 2; q++)
                w2[q] = *(const unsigned long long*)&Ws[kk][q * 32 + tx * 2];
#pragma unroll
            for (int rr = 0; rr < 4; rr++)
#pragma unroll
                for (int q = 0; q < 2; q++)
                    ffma2(acc[rr][q], a2[rr], w2[q]);
        }
        __syncthreads();
    }

#pragma unroll
    for (int rr = 0; rr < 4; rr++) {
        int n = n0 + ty + 16 * rr;
#pragma unroll
        for (int q = 0; q < 2; q++) {
            float z0, z1;
            unpack2(acc[rr][q], z0, z1);
#pragma unroll
            for (int h = 0; h < 2; h++) {
                int o = q * 32 + tx * 2 + h;
                float z = (h == 0 ? z0 : z1) + b2[o];
                float c = tanhf(z);
                size_t off = (size_t)b * (NN * UU) + (size_t)n * UU + o;
                float u = g_U[off];
                float hv = hx[off];
                out[off] = u * hv + (1.0f - u) * c;
            }
        }
    }
}

// ---------------- launcher ----------------
extern "C" void kernel_launch(void* const* d_in, const int* in_sizes, int n_in,
                              void* d_out, int out_size) {
    const float* inputs = (const float*)d_in[0];
    const float* hx     = (const float*)d_in[1];
    const float* s0     = (const float*)d_in[2];
    const float* s1     = (const float*)d_in[3];
    const float* W      = (const float*)d_in[4];
    const float* bias   = (const float*)d_in[5];
    const float* W2     = (const float*)d_in[6];
    const float* b2     = (const float*)d_in[7];
    float* out = (float*)d_out;

    build_sparse_k<<<NN / 8, 256>>>(s0, 0);
    build_sparse_k<<<NN / 8, 256>>>(s1, 1);
    build_x_k<<<(NN * FB + 255) / 256, 256>>>(inputs, hx);

    // gconv1
    spmm_k<<<NN, 264>>>(0, 0, -1, 1, 1.0f);  // M0 = S0 @ X0
    spmm_k<<<NN, 264>>>(0, 1,  0, 2, 2.0f);  // M1 = 2*S0 @ M0 - X0
    spmm_k<<<NN, 264>>>(1, 0, -1, 3, 1.0f);  // M2 = S1 @ X0
    spmm_k<<<NN, 264>>>(1, 3,  0, 4, 2.0f);  // M3 = 2*S1 @ M2 - X0

    proj1_k<<<dim3(NN / 64, BB), 256>>>(W, bias, hx);

    // gconv2
    spmm_k<<<NN, 264>>>(0, 5, -1, 1, 1.0f);
    spmm_k<<<NN, 264>>>(0, 1,  5, 2, 2.0f);
    spmm_k<<<NN, 264>>>(1, 5, -1, 3, 1.0f);
    spmm_k<<<NN, 264>>>(1, 3,  5, 4, 2.0f);

    proj2_k<<<dim3(NN / 64, BB), 256>>>(W2, b2, hx, out);
}

// round 14
// speedup vs baseline: 1.9590x; 1.0275x over previous
#include <cuda_runtime.h>
#include <cuda_bf16.h>
#include <cstdint>
#include <math.h>

#define NN 4096
#define BB 32
#define FF 66
#define UU 64
#define MM 5
#define FB 2112          // FF*BB
#define FBQ 264          // FB/8 uint4 (8 bf16) per row
#define NNZ_MAX 128

// ---------------- scratch ----------------
__device__ uint4 g_X0b[(size_t)NN * FBQ];
__device__ uint4 g_X2b[(size_t)NN * FBQ];
__device__ uint4 g_Mb[4][(size_t)NN * FBQ];   // [0]=S0@X, [1]=cheb(S0), [2]=S1@X, [3]=cheb(S1)
__device__ float g_U[(size_t)BB * NN * UU];
__device__ int2  g_sp[2][(size_t)NNZ_MAX * NN];  // packed {col_idx, val_bits}
__device__ int   g_cnt[2][NN];

// ---------------- packed f32x2 helpers ----------------
__device__ __forceinline__ unsigned long long pack2(float lo, float hi) {
    unsigned long long r;
    asm("mov.b64 %0, {%1, %2};" : "=l"(r) : "f"(lo), "f"(hi));
    return r;
}
__device__ __forceinline__ void unpack2(unsigned long long v, float& lo, float& hi) {
    asm("mov.b64 {%0, %1}, %2;" : "=f"(lo), "=f"(hi) : "l"(v));
}
__device__ __forceinline__ void ffma2(unsigned long long& d, unsigned long long a,
                                      unsigned long long b) {
    asm("fma.rn.f32x2 %0, %1, %2, %0;" : "+l"(d) : "l"(a), "l"(b));
}
// bf16x2 (one u32) -> packed f32x2 (u64); bf16->f32 is an exact 16-bit shift.
__device__ __forceinline__ unsigned long long bf2_to_f32x2(unsigned p) {
    unsigned long long r;
    asm("{ .reg .b32 lo, hi;\n\t"
        "prmt.b32 lo, %1, 0, 0x1044;\n\t"
        "prmt.b32 hi, %1, 0, 0x3244;\n\t"
        "mov.b64 %0, {lo, hi}; }" : "=l"(r) : "r"(p));
    return r;
}

// ---------------- sparse build (packed pairs) ----------------
__global__ void build_sparse_k(const float* __restrict__ S, int sup) {
    int gw   = (blockIdx.x * blockDim.x + threadIdx.x) >> 5;
    int lane = threadIdx.x & 31;
    if (gw >= NN) return;
    const float* row = S + (size_t)gw * NN;
    int2* sp = g_sp[sup];
    int c = 0;
    for (int j0 = 0; j0 < NN; j0 += 32) {
        float v = row[j0 + lane];
        unsigned m = __ballot_sync(0xffffffffu, v != 0.0f);
        int pre = __popc(m & ((1u << lane) - 1u));
        if (v != 0.0f) {
            int slot = c + pre;
            if (slot < NNZ_MAX)
                sp[(size_t)slot * NN + gw] = make_int2(j0 + lane, __float_as_int(v));
        }
        c += __popc(m);
    }
    if (lane == 0) g_cnt[sup][gw] = (c < NNZ_MAX) ? c : NNZ_MAX;
}

// ---------------- build X0 / static X2 (bf16) ----------------
__global__ void build_x_k(const float* __restrict__ inp, const float* __restrict__ hx) {
    int e = blockIdx.x * blockDim.x + threadIdx.x;
    if (e >= NN * FB) return;
    int n = e / FB;
    int rem = e - n * FB;
    int b = rem / FF;
    int f = rem - b * FF;
    __nv_bfloat16* X0 = (__nv_bfloat16*)g_X0b;
    __nv_bfloat16* X2 = (__nv_bfloat16*)g_X2b;
    float v;
    if (f < 2) {
        v = inp[(size_t)b * (NN * 2) + n * 2 + f];
        X2[e] = __float2bfloat16(v);
    } else {
        v = hx[(size_t)b * (NN * UU) + (size_t)n * UU + (f - 2)];
    }
    X0[e] = __float2bfloat16(v);
}

__device__ __forceinline__ uint4* x_buf(int s) { return s ? g_X2b : g_X0b; }

// ---------------- dual-support SpMM, packed FFMA2 accumulation -----------------
// grid (NN, 2): blockIdx.y = support. phase 0: M[2s] = S_s @ X(xsel).
// phase 1: M[2s+1] = 2 * S_s @ M[2s] - X(xsel).
__device__ __forceinline__ void fma8p(unsigned long long* acc, uint4 x,
                                      unsigned long long v2) {
    const unsigned* p = (const unsigned*)&x;
#pragma unroll
    for (int q = 0; q < 4; q++)
        ffma2(acc[q], v2, bf2_to_f32x2(p[q]));
}

__global__ __launch_bounds__(264) void spmm2_k(int phase, int xsel) {
    int sup = blockIdx.y;
    int i = blockIdx.x;
    int t = threadIdx.x;  // 0..263: one uint4 (8 bf16) = full row coverage
    const uint4* __restrict__ Xin = phase ? g_Mb[2 * sup] : x_buf(xsel);
    uint4* __restrict__ Yout = g_Mb[2 * sup + phase];
    const int2* __restrict__ sp = g_sp[sup];
    int cnt = g_cnt[sup][i];
    float alpha = phase ? 2.0f : 1.0f;

    unsigned long long acc[4];
#pragma unroll
    for (int q = 0; q < 4; q++) acc[q] = 0ULL;

    int k = 0;
    for (; k + 3 < cnt; k += 4) {
        int2 p0 = __ldg(&sp[(size_t)(k + 0) * NN + i]);
        int2 p1 = __ldg(&sp[(size_t)(k + 1) * NN + i]);
        int2 p2 = __ldg(&sp[(size_t)(k + 2) * NN + i]);
        int2 p3 = __ldg(&sp[(size_t)(k + 3) * NN + i]);
        uint4 x0 = __ldg(&Xin[(size_t)p0.x * FBQ + t]);
        uint4 x1 = __ldg(&Xin[(size_t)p1.x * FBQ + t]);
        uint4 x2 = __ldg(&Xin[(size_t)p2.x * FBQ + t]);
        uint4 x3 = __ldg(&Xin[(size_t)p3.x * FBQ + t]);
        float v0 = __int_as_float(p0.y), v1 = __int_as_float(p1.y);
        float v2 = __int_as_float(p2.y), v3 = __int_as_float(p3.y);
        fma8p(acc, x0, pack2(v0, v0));
        fma8p(acc, x1, pack2(v1, v1));
        fma8p(acc, x2, pack2(v2, v2));
        fma8p(acc, x3, pack2(v3, v3));
    }
    for (; k < cnt; k++) {
        int2 p = __ldg(&sp[(size_t)k * NN + i]);
        uint4 x = __ldg(&Xin[(size_t)p.x * FBQ + t]);
        float v = __int_as_float(p.y);
        fma8p(acc, x, pack2(v, v));
    }

    float r[8];
#pragma unroll
    for (int q = 0; q < 4; q++) {
        float lo, hi;
        unpack2(acc[q], lo, hi);
        r[2 * q] = alpha * lo;
        r[2 * q + 1] = alpha * hi;
    }
    if (phase) {
        const uint4* Xs = x_buf(xsel);
        uint4 s = __ldg(&Xs[(size_t)i * FBQ + t]);
        const __nv_bfloat162* ps = (const __nv_bfloat162*)&s;
#pragma unroll
        for (int q = 0; q < 4; q++) {
            float2 f = __bfloat1622float2(ps[q]);
            r[2 * q]     -= f.x;
            r[2 * q + 1] -= f.y;
        }
    }
    uint4 o;
    __nv_bfloat162* po = (__nv_bfloat162*)&o;
#pragma unroll
    for (int q = 0; q < 4; q++)
        po[q] = __floats2bfloat162_rn(r[2 * q], r[2 * q + 1]);
    Yout[(size_t)i * FBQ + t] = o;
}

// ---------------- proj1: FFMA2 GEMM, 64 rows x 128 cols per CTA (R13) ----------
__global__ __launch_bounds__(256) void proj1_k(const float* __restrict__ W,
                                               const float* __restrict__ bias,
                                               const float* __restrict__ hx) {
    __shared__ float As[64][68];
    __shared__ float Ws[66][128];
    int b = blockIdx.y;
    int n0 = blockIdx.x * 64;
    int t = threadIdx.x;
    int tx = t & 15, ty = t >> 4;

    unsigned long long acc[4][4];
#pragma unroll
    for (int rr = 0; rr < 4; rr++)
#pragma unroll
        for (int q = 0; q < 4; q++) acc[rr][q] = 0ULL;

#pragma unroll 1
    for (int m = 0; m < MM; m++) {
        const __nv_bfloat16* Am = (const __nv_bfloat16*)((m == 0) ? g_X0b : g_Mb[m - 1]);
        for (int e = t; e < 64 * FF; e += 256) {
            int r = e / FF, f = e - r * FF;
            As[r][f] = __bfloat162float(Am[(size_t)(n0 + r) * FB + b * FF + f]);
        }
        for (int e = t; e < FF * 128; e += 256) {
            int f = e >> 7, o = e & 127;
            Ws[f][o] = W[(size_t)(f * MM + m) * 128 + o];
        }
        __syncthreads();
#pragma unroll 6
        for (int kk = 0; kk < FF; kk++) {
            unsigned long long a2[4];
#pragma unroll
            for (int rr = 0; rr < 4; rr++) {
                float a = As[ty + 16 * rr][kk];
                a2[rr] = pack2(a, a);
            }
            unsigned long long w2[4];
#pragma unroll
            for (int q = 0; q < 4; q++)
                w2[q] = *(const unsigned long long*)&Ws[kk][q * 32 + tx * 2];
#pragma unroll
            for (int rr = 0; rr < 4; rr++)
#pragma unroll
                for (int q = 0; q < 4; q++)
                    ffma2(acc[rr][q], a2[rr], w2[q]);
        }
        __syncthreads();
    }

    __nv_bfloat16* X2 = (__nv_bfloat16*)g_X2b;
#pragma unroll
    for (int rr = 0; rr < 4; rr++) {
        int n = n0 + ty + 16 * rr;
#pragma unroll
        for (int q = 0; q < 4; q++) {
            float z0, z1;
            unpack2(acc[rr][q], z0, z1);
#pragma unroll
            for (int h = 0; h < 2; h++) {
                int o = q * 32 + tx * 2 + h;
                float z = (h == 0 ? z0 : z1) + bias[o];
                float s = 1.0f / (1.0f + expf(-z));
                if (o < UU) {
                    float hv = hx[(size_t)b * (NN * UU) + (size_t)n * UU + o];
                    X2[(size_t)n * FB + b * FF + 2 + o] = __float2bfloat16(s * hv);
                } else {
                    g_U[(size_t)b * (NN * UU) + (size_t)n * UU + (o - UU)] = s;
                }
            }
        }
    }
}

// ---------------- proj2: FFMA2 GEMM, 64 rows x 64 cols per CTA (R13) -----------
__global__ __launch_bounds__(256) void proj2_k(const float* __restrict__ W2,
                                               const float* __restrict__ b2,
                                               const float* __restrict__ hx,
                                               float* __restrict__ out) {
    __shared__ float As[64][68];
    __shared__ float Ws[66][64];
    int b = blockIdx.y;
    int n0 = blockIdx.x * 64;
    int t = threadIdx.x;
    int tx = t & 15, ty = t >> 4;

    unsigned long long acc[4][2];
#pragma unroll
    for (int rr = 0; rr < 4; rr++)
#pragma unroll
        for (int q = 0; q < 2; q++) acc[rr][q] = 0ULL;

#pragma unroll 1
    for (int m = 0; m < MM; m++) {
        const __nv_bfloat16* Am = (const __nv_bfloat16*)((m == 0) ? g_X2b : g_Mb[m - 1]);
        for (int e = t; e < 64 * FF; e += 256) {
            int r = e / FF, f = e - r * FF;
            As[r][f] = __bfloat162float(Am[(size_t)(n0 + r) * FB + b * FF + f]);
        }
        for (int e = t; e < FF * 64; e += 256) {
            int f = e >> 6, o = e & 63;
            Ws[f][o] = W2[(size_t)(f * MM + m) * 64 + o];
        }
        __syncthreads();
#pragma unroll 6
        for (int kk = 0; kk < FF; kk++) {
            unsigned long long a2[4];
#pragma unroll
            for (int rr = 0; rr < 4; rr++) {
                float a = As[ty + 16 * rr][kk];
                a2[rr] = pack2(a, a);
            }
            unsigned long long w2[2];
#pragma unroll
            for (int q = 0; q < 2; q++)
                w2[q] = *(const unsigned long long*)&Ws[kk][q * 32 + tx * 2];
#pragma unroll
            for (int rr = 0; rr < 4; rr++)
#pragma unroll
                for (int q = 0; q < 2; q++)
                    ffma2(acc[rr][q], a2[rr], w2[q]);
        }
        __syncthreads();
    }

#pragma unroll
    for (int rr = 0; rr < 4; rr++) {
        int n = n0 + ty + 16 * rr;
#pragma unroll
        for (int q = 0; q < 2; q++) {
            float z0, z1;
            unpack2(acc[rr][q], z0, z1);
#pragma unroll
            for (int h = 0; h < 2; h++) {
                int o = q * 32 + tx * 2 + h;
                float z = (h == 0 ? z0 : z1) + b2[o];
                float c = tanhf(z);
                size_t off = (size_t)b * (NN * UU) + (size_t)n * UU + o;
                float u = g_U[off];
                float hv = hx[off];
                out[off] = u * hv + (1.0f - u) * c;
            }
        }
    }
}

// ---------------- launcher ----------------
extern "C" void kernel_launch(void* const* d_in, const int* in_sizes, int n_in,
                              void* d_out, int out_size) {
    const float* inputs = (const float*)d_in[0];
    const float* hx     = (const float*)d_in[1];
    const float* s0     = (const float*)d_in[2];
    const float* s1     = (const float*)d_in[3];
    const float* W      = (const float*)d_in[4];
    const float* bias   = (const float*)d_in[5];
    const float* W2     = (const float*)d_in[6];
    const float* b2     = (const float*)d_in[7];
    float* out = (float*)d_out;

    build_sparse_k<<<NN / 8, 256>>>(s0, 0);
    build_sparse_k<<<NN / 8, 256>>>(s1, 1);
    build_x_k<<<(NN * FB + 255) / 256, 256>>>(inputs, hx);

    dim3 sgrid(NN, 2);
    // gconv1 (xsel 0 = X0)
    spmm2_k<<<sgrid, 264>>>(0, 0);  // M0 = S0@X0, M2 = S1@X0
    spmm2_k<<<sgrid, 264>>>(1, 0);  // M1 = 2*S0@M0 - X0, M3 = 2*S1@M2 - X0

    proj1_k<<<dim3(NN / 64, BB), 256>>>(W, bias, hx);

    // gconv2 (xsel 1 = X2)
    spmm2_k<<<sgrid, 264>>>(0, 1);
    spmm2_k<<<sgrid, 264>>>(1, 1);

    proj2_k<<<dim3(NN / 64, BB), 256>>>(W2, b2, hx, out);
}